// round 7
// baseline (speedup 1.0000x reference)
#include <cuda_runtime.h>

#define B_ 16
#define N_ 4096
#define M_ 4096
#define D_ 64
#define ROWS_ (B_ * N_)
#define TILE_R 128
#define TILE_M 64
#define THREADS 128

// Precomputed ||c||^2 per code. __device__ global scratch (no allocation).
__device__ float g_c2[M_];

__global__ void c2_kernel(const float* __restrict__ codes) {
    int m = blockIdx.x * blockDim.x + threadIdx.x;
    if (m < M_) {
        const float4* p = reinterpret_cast<const float4*>(codes + (size_t)m * D_);
        float s = 0.f;
#pragma unroll
        for (int i = 0; i < D_ / 4; i++) {
            float4 v = p[i];
            s = fmaf(v.x, v.x, s);
            s = fmaf(v.y, v.y, s);
            s = fmaf(v.z, v.z, s);
            s = fmaf(v.w, v.w, s);
        }
        g_c2[m] = s;
    }
}

extern __shared__ float smem[];

__global__ __launch_bounds__(THREADS) void nn_kernel(
    const float* __restrict__ x, const float* __restrict__ codes,
    float* __restrict__ out)
{
    // smem (K-major transposed, conflict-free LDS.128):
    //   xs [D_][TILE_R] : 64*128 floats = 32768 B
    //   cs [D_][TILE_M] : 64*64  floats = 16384 B
    // total = 49152 B == default dynamic-smem limit (NO opt-in needed)
    float* xs = smem;
    float* cs = smem + D_ * TILE_R;

    const int tid = threadIdx.x;
    const int ty  = tid >> 3;   // 0..15 -> row group (8 rows)
    const int tx  = tid & 7;    // 0..7  -> code group (8 codes)
    const int row0 = blockIdx.x * TILE_R;
    const int r0 = ty * 8;
    const int c0 = tx * 8;

    // Load x tile once, transposing to xs[k][r].
    for (int i = tid; i < TILE_R * D_; i += THREADS) {
        int r = i >> 6;          // / 64
        int k = i & 63;          // % 64
        xs[k * TILE_R + r] = x[(size_t)(row0 + r) * D_ + k];
    }

    float minv[8];
    int   mini[8];
#pragma unroll
    for (int i = 0; i < 8; i++) { minv[i] = 3.4e38f; mini[i] = 0; }

    for (int mt = 0; mt < M_; mt += TILE_M) {
        // Load code tile, transposing to cs[k][c].
        for (int i = tid; i < TILE_M * D_; i += THREADS) {
            int c = i >> 6;
            int k = i & 63;
            cs[k * TILE_M + c] = codes[(size_t)(mt + c) * D_ + k];
        }
        __syncthreads();

        float acc[8][8];
#pragma unroll
        for (int i = 0; i < 8; i++)
#pragma unroll
            for (int j = 0; j < 8; j++) acc[i][j] = 0.f;

#pragma unroll 4
        for (int k = 0; k < D_; k++) {
            float a[8], b[8];
            float4 a0 = *reinterpret_cast<float4*>(&xs[k * TILE_R + r0]);
            float4 a1 = *reinterpret_cast<float4*>(&xs[k * TILE_R + r0 + 4]);
            float4 b0 = *reinterpret_cast<float4*>(&cs[k * TILE_M + c0]);
            float4 b1 = *reinterpret_cast<float4*>(&cs[k * TILE_M + c0 + 4]);
            a[0] = a0.x; a[1] = a0.y; a[2] = a0.z; a[3] = a0.w;
            a[4] = a1.x; a[5] = a1.y; a[6] = a1.z; a[7] = a1.w;
            b[0] = b0.x; b[1] = b0.y; b[2] = b0.z; b[3] = b0.w;
            b[4] = b1.x; b[5] = b1.y; b[6] = b1.z; b[7] = b1.w;
#pragma unroll
            for (int i = 0; i < 8; i++)
#pragma unroll
                for (int j = 0; j < 8; j++)
                    acc[i][j] = fmaf(a[i], b[j], acc[i][j]);
        }

        // Fused epilogue: track min over codes of (c^2 - 2*dot).
        // Codes visited in increasing index; strict '<' preserves argmin
        // first-occurrence semantics.
#pragma unroll
        for (int j = 0; j < 8; j++) {
            float c2 = __ldg(&g_c2[mt + c0 + j]);
            int code = mt + c0 + j;
#pragma unroll
            for (int i = 0; i < 8; i++) {
                float t = fmaf(-2.f, acc[i][j], c2);
                if (t < minv[i]) { minv[i] = t; mini[i] = code; }
            }
        }
        __syncthreads();
    }

    // Cross-thread reduction: 8 lanes (tx=0..7) share each row group.
    // lane = (ty&3)*8 + tx, so xor offsets 4,2,1 stay inside the group.
#pragma unroll
    for (int i = 0; i < 8; i++) {
        float v = minv[i];
        int idx = mini[i];
#pragma unroll
        for (int off = 4; off > 0; off >>= 1) {
            float ov = __shfl_xor_sync(0xffffffffu, v, off);
            int   oi = __shfl_xor_sync(0xffffffffu, idx, off);
            if (ov < v || (ov == v && oi < idx)) { v = ov; idx = oi; }
        }
        if (tx == 0) {
            int row = r0 + i;
            float x2 = 0.f;
#pragma unroll 8
            for (int k = 0; k < D_; k++) {
                float xv = xs[k * TILE_R + row];
                x2 = fmaf(xv, xv, x2);
            }
            float d2min = x2 + v;
            // Output dtype is float32: NaN rel_err came from int -1
            // (0xFFFFFFFF) being reinterpreted as float NaN.
            out[row0 + row] = (d2min <= 0.1f) ? (float)idx : -1.0f;
        }
    }
}

extern "C" void kernel_launch(void* const* d_in, const int* in_sizes, int n_in,
                              void* d_out, int out_size) {
    const float* x     = (const float*)d_in[0];  // [16,4096,64] f32
    const float* codes = (const float*)d_in[1];  // [4096,64]    f32
    float* out = (float*)d_out;                  // [16,4096]    float32 output

    (void)in_sizes; (void)n_in; (void)out_size;

    c2_kernel<<<(M_ + 255) / 256, 256>>>(codes);

    const int smem_bytes = (D_ * TILE_R + D_ * TILE_M) * (int)sizeof(float); // 49152
    nn_kernel<<<ROWS_ / TILE_R, THREADS, smem_bytes>>>(x, codes, out);
}

// round 11
// speedup vs baseline: 8.5464x; 8.5464x over previous
#include <cuda_runtime.h>
#include <cuda_bf16.h>
#include <cstdint>

#define B_ 16
#define N_ 4096
#define M_ 4096
#define D_ 64
#define ROWS_ (B_ * N_)
#define TILE_R 128
#define TILE_N 64
#define NT (M_ / TILE_N)     // 64 code tiles
#define THREADS 256

// ---------------- device globals (no allocation allowed) ----------------
__device__ float         g_c2[M_];
__device__ __nv_bfloat16 g_codes_bf16[M_ * D_];

__device__ __forceinline__ uint32_t smem_u32(const void* p) {
    uint32_t a;
    asm("{ .reg .u64 t; cvta.to.shared.u64 t, %1; cvt.u32.u64 %0, t; }" : "=r"(a) : "l"(p));
    return a;
}
// 128B-row swizzle: rows land in distinct 16B bank groups -> conflict-free ldmatrix
__device__ __forceinline__ uint32_t swz(uint32_t o) { return o ^ ((o >> 3) & 0x70); }

#define LDSM4(d0, d1, d2, d3, a)                                              \
    asm volatile("ldmatrix.sync.aligned.m8n8.x4.shared.b16 {%0,%1,%2,%3}, [%4];" \
        : "=r"(d0), "=r"(d1), "=r"(d2), "=r"(d3) : "r"(a))

#define MMA16816(d0, d1, d2, d3, a0, a1, a2, a3, b0, b1)                      \
    asm volatile("mma.sync.aligned.m16n8k16.row.col.f32.bf16.bf16.f32 "       \
        "{%0,%1,%2,%3}, {%4,%5,%6,%7}, {%8,%9}, {%0,%1,%2,%3};"               \
        : "+f"(d0), "+f"(d1), "+f"(d2), "+f"(d3)                              \
        : "r"(a0), "r"(a1), "r"(a2), "r"(a3), "r"(b0), "r"(b1))

// ---------------- prepass: c2 + bf16 codes ----------------
__global__ void prep_codes(const float* __restrict__ codes) {
    int m = blockIdx.x * blockDim.x + threadIdx.x;
    if (m >= M_) return;
    const float4* p = reinterpret_cast<const float4*>(codes + (size_t)m * D_);
    __nv_bfloat162* dst = reinterpret_cast<__nv_bfloat162*>(g_codes_bf16 + (size_t)m * D_);
    float s = 0.f;
#pragma unroll
    for (int i = 0; i < D_ / 4; i++) {
        float4 v = p[i];
        s = fmaf(v.x, v.x, s); s = fmaf(v.y, v.y, s);
        s = fmaf(v.z, v.z, s); s = fmaf(v.w, v.w, s);
        dst[i * 2]     = __floats2bfloat162_rn(v.x, v.y);
        dst[i * 2 + 1] = __floats2bfloat162_rn(v.z, v.w);
    }
    g_c2[m] = s;
}

__global__ __launch_bounds__(THREADS) void nn_kernel(
    const float* __restrict__ x, float* __restrict__ out)
{
    // static smem = 16K + 2*8K + 16K = 49152 B (= 48KB static limit, no opt-in)
    __shared__ __align__(16) char  sx[TILE_R * 128];       // x tile bf16, 128B/row, swizzled
    __shared__ __align__(16) char  sb[2][TILE_N * 128];    // code tiles bf16, double buffered
    __shared__ __align__(16) float sc2[M_];                // full ||c||^2 table

    const int tid  = threadIdx.x;
    const int lane = tid & 31;
    const int wid  = tid >> 5;        // 8 warps
    const int wr0  = wid * 16;        // warp's 16-row group
    const int row0 = blockIdx.x * TILE_R;

    const uint32_t sxu  = smem_u32(sx);
    const uint32_t sbu0 = smem_u32(sb[0]);
    const uint32_t sbu1 = smem_u32(sb[1]);

    // ---- load x tile fp32->bf16, swizzled (128 rows x 32 pairs) ----
#pragma unroll
    for (int j = 0; j < 16; j++) {
        int idx = tid + j * THREADS;          // 4096 pairs
        int r = idx >> 5, p = idx & 31;
        float2 v = *reinterpret_cast<const float2*>(x + (size_t)(row0 + r) * D_ + p * 2);
        uint32_t pk;
        asm("cvt.rn.bf16x2.f32 %0, %1, %2;" : "=r"(pk) : "f"(v.y), "f"(v.x));
        *reinterpret_cast<uint32_t*>(sx + swz(r * 128 + p * 4)) = pk;
    }
    // ---- c2 table ----
#pragma unroll
    for (int j = 0; j < 4; j++) {
        int idx = tid + j * THREADS;          // 1024 float4
        *reinterpret_cast<float4*>(sc2 + idx * 4) =
            *reinterpret_cast<const float4*>(g_c2 + idx * 4);
    }
    // ---- first B tile ----
    {
        const uint4* src = reinterpret_cast<const uint4*>(g_codes_bf16);
#pragma unroll
        for (int i = 0; i < 2; i++) {
            int idx = tid + i * THREADS;      // 512 uint4
            int r = idx >> 3, q = idx & 7;
            uint4 v = src[idx];
            *reinterpret_cast<uint4*>(sb[0] + swz(r * 128 + q * 16)) = v;
        }
    }
    __syncthreads();

    // ---- A fragments for all 4 k-steps (held in regs whole kernel) ----
    uint32_t a[16];
    {
        int arow = wr0 + (lane & 7) + ((lane >> 3) & 1) * 8;
        int akb  = ((lane >> 4) & 1) * 16;
#pragma unroll
        for (int kk = 0; kk < 4; kk++) {
            uint32_t addr = sxu + swz(arow * 128 + kk * 32 + akb);
            LDSM4(a[kk * 4 + 0], a[kk * 4 + 1], a[kk * 4 + 2], a[kk * 4 + 3], addr);
        }
    }

    // min state: this thread owns rows (wr0 + lane/4) and (+8)
    float vlo = 3.4e38f, vhi = 3.4e38f;
    int   ilo = 0,       ihi = 0;

    const int brl = lane & 7;                 // ldmatrix row-within-8
    const int bkb = (lane >> 3) * 16;         // k-chunk per lane group
    const int cq  = (lane & 3) * 2;           // this thread's column pair offset

    for (int t = 0; t < NT; t++) {
        const uint32_t sbu = (t & 1) ? sbu1 : sbu0;

        // prefetch next B tile into regs (overlaps with mma below)
        uint4 pf0, pf1;
        if (t + 1 < NT) {
            const uint4* src = reinterpret_cast<const uint4*>(
                g_codes_bf16 + (size_t)(t + 1) * TILE_N * D_);
            pf0 = src[tid];
            pf1 = src[tid + THREADS];
        }

#pragma unroll
        for (int j = 0; j < 8; j++) {         // 8 n-fragments of 8 codes
            uint32_t b0, b1, b2, b3, b4, b5, b6, b7;
            uint32_t base = (j * 8 + brl) * 128;
            LDSM4(b0, b1, b2, b3, sbu + swz(base + bkb));
            LDSM4(b4, b5, b6, b7, sbu + swz(base + 64 + bkb));

            float d0 = 0.f, d1 = 0.f, d2 = 0.f, d3 = 0.f;
            MMA16816(d0, d1, d2, d3, a[0],  a[1],  a[2],  a[3],  b0, b1);
            MMA16816(d0, d1, d2, d3, a[4],  a[5],  a[6],  a[7],  b2, b3);
            MMA16816(d0, d1, d2, d3, a[8],  a[9],  a[10], a[11], b4, b5);
            MMA16816(d0, d1, d2, d3, a[12], a[13], a[14], a[15], b6, b7);

            // fused epilogue: v = c2 - 2*dot ; codes ascend -> strict '<'
            const int c = t * TILE_N + j * 8 + cq;
            float2 c2p = *reinterpret_cast<const float2*>(sc2 + c);
            float v0 = fmaf(-2.f, d0, c2p.x);
            float v1 = fmaf(-2.f, d1, c2p.y);
            float v2 = fmaf(-2.f, d2, c2p.x);
            float v3 = fmaf(-2.f, d3, c2p.y);
            if (v0 < vlo) { vlo = v0; ilo = c; }
            if (v1 < vlo) { vlo = v1; ilo = c + 1; }
            if (v2 < vhi) { vhi = v2; ihi = c; }
            if (v3 < vhi) { vhi = v3; ihi = c + 1; }
        }

        __syncthreads();                      // all warps done reading other buffer
        if (t + 1 < NT) {
            char* dst = sb[(t + 1) & 1];
            int r0i = tid >> 3, q0 = tid & 7;
            int r1i = (tid + THREADS) >> 3, q1 = tid & 7;
            *reinterpret_cast<uint4*>(dst + swz(r0i * 128 + q0 * 16)) = pf0;
            *reinterpret_cast<uint4*>(dst + swz(r1i * 128 + q1 * 16)) = pf1;
            __syncthreads();
        }
    }

    // ---- quad reduction (lanes 4k..4k+3 share rows), lower-index tie-break ----
#pragma unroll
    for (int off = 1; off <= 2; off <<= 1) {
        float ov = __shfl_xor_sync(0xffffffffu, vlo, off);
        int   oi = __shfl_xor_sync(0xffffffffu, ilo, off);
        if (ov < vlo || (ov == vlo && oi < ilo)) { vlo = ov; ilo = oi; }
        ov = __shfl_xor_sync(0xffffffffu, vhi, off);
        oi = __shfl_xor_sync(0xffffffffu, ihi, off);
        if (ov < vhi || (ov == vhi && oi < ihi)) { vhi = ov; ihi = oi; }
    }

    if ((lane & 3) == 0) {
        const int rlo = wr0 + (lane >> 2);
        const int rhi = rlo + 8;
        float x2lo = 0.f, x2hi = 0.f;
        const float* xlo = x + (size_t)(row0 + rlo) * D_;
        const float* xhi = x + (size_t)(row0 + rhi) * D_;
#pragma unroll
        for (int i = 0; i < D_ / 4; i++) {
            float4 u = *reinterpret_cast<const float4*>(xlo + i * 4);
            float4 w = *reinterpret_cast<const float4*>(xhi + i * 4);
            x2lo = fmaf(u.x, u.x, x2lo); x2lo = fmaf(u.y, u.y, x2lo);
            x2lo = fmaf(u.z, u.z, x2lo); x2lo = fmaf(u.w, u.w, x2lo);
            x2hi = fmaf(w.x, w.x, x2hi); x2hi = fmaf(w.y, w.y, x2hi);
            x2hi = fmaf(w.z, w.z, x2hi); x2hi = fmaf(w.w, w.w, x2hi);
        }
        out[row0 + rlo] = (x2lo + vlo <= 0.1f) ? (float)ilo : -1.0f;
        out[row0 + rhi] = (x2hi + vhi <= 0.1f) ? (float)ihi : -1.0f;
    }
}

extern "C" void kernel_launch(void* const* d_in, const int* in_sizes, int n_in,
                              void* d_out, int out_size) {
    const float* x     = (const float*)d_in[0];  // [16,4096,64] f32
    const float* codes = (const float*)d_in[1];  // [4096,64]    f32
    float* out = (float*)d_out;                  // [16,4096]    f32

    (void)in_sizes; (void)n_in; (void)out_size;

    prep_codes<<<M_ / 256, 256>>>(codes);
    nn_kernel<<<ROWS_ / TILE_R, THREADS>>>(x, out);
}

// round 15
// speedup vs baseline: 9.7028x; 1.1353x over previous
#include <cuda_runtime.h>
#include <cuda_bf16.h>
#include <cstdint>

#define B_ 16
#define N_ 4096
#define M_ 4096
#define D_ 64
#define ROWS_ (B_ * N_)
#define TILE_R 128
#define TILE_N 128
#define NT (M_ / TILE_N)     // 32 code tiles
#define THREADS 256

// ---------------- device globals (no allocation allowed) ----------------
__device__ float         g_h[M_];                 // -0.5 * ||c||^2
__device__ __nv_bfloat16 g_codes_bf16[M_ * D_];

__device__ __forceinline__ uint32_t smem_u32(const void* p) {
    uint32_t a;
    asm("{ .reg .u64 t; cvta.to.shared.u64 t, %1; cvt.u32.u64 %0, t; }" : "=r"(a) : "l"(p));
    return a;
}
// 128B-row swizzle; note swz(o + k*1024) == swz(o) + k*1024 (bits 7..9 untouched)
__device__ __forceinline__ uint32_t swz(uint32_t o) { return o ^ ((o >> 3) & 0x70); }

#define LDSM4(d0, d1, d2, d3, a)                                                 \
    asm volatile("ldmatrix.sync.aligned.m8n8.x4.shared.b16 {%0,%1,%2,%3}, [%4];" \
        : "=r"(d0), "=r"(d1), "=r"(d2), "=r"(d3) : "r"(a))

// accumulate in place
#define MMA16816(d0, d1, d2, d3, a0, a1, a2, a3, b0, b1)                         \
    asm volatile("mma.sync.aligned.m16n8k16.row.col.f32.bf16.bf16.f32 "          \
        "{%0,%1,%2,%3}, {%4,%5,%6,%7}, {%8,%9}, {%0,%1,%2,%3};"                  \
        : "+f"(d0), "+f"(d1), "+f"(d2), "+f"(d3)                                 \
        : "r"(a0), "r"(a1), "r"(a2), "r"(a3), "r"(b0), "r"(b1))

// first MMA of the chain: C = {h0,h1,h0,h1}  (accumulator pre-loaded with -c^2/2)
#define MMA_INIT(d0, d1, d2, d3, a0, a1, a2, a3, b0, b1, c0, c1)                 \
    asm volatile("mma.sync.aligned.m16n8k16.row.col.f32.bf16.bf16.f32 "          \
        "{%0,%1,%2,%3}, {%4,%5,%6,%7}, {%8,%9}, {%10,%11,%12,%13};"              \
        : "=f"(d0), "=f"(d1), "=f"(d2), "=f"(d3)                                 \
        : "r"(a0), "r"(a1), "r"(a2), "r"(a3), "r"(b0), "r"(b1),                  \
          "f"(c0), "f"(c1), "f"(c0), "f"(c1))

#define CP_ASYNC16(dst, src) \
    asm volatile("cp.async.cg.shared.global [%0], [%1], 16;" :: "r"(dst), "l"(src) : "memory")
#define CP_COMMIT() asm volatile("cp.async.commit_group;" ::: "memory")
#define CP_WAIT0()  asm volatile("cp.async.wait_group 0;" ::: "memory")

// ---------------- prepass: h = -c2/2 + bf16 codes ----------------
__global__ void prep_codes(const float* __restrict__ codes) {
    int m = blockIdx.x * blockDim.x + threadIdx.x;
    if (m >= M_) return;
    const float4* p = reinterpret_cast<const float4*>(codes + (size_t)m * D_);
    __nv_bfloat162* dst = reinterpret_cast<__nv_bfloat162*>(g_codes_bf16 + (size_t)m * D_);
    float s = 0.f;
#pragma unroll
    for (int i = 0; i < D_ / 4; i++) {
        float4 v = p[i];
        s = fmaf(v.x, v.x, s); s = fmaf(v.y, v.y, s);
        s = fmaf(v.z, v.z, s); s = fmaf(v.w, v.w, s);
        dst[i * 2]     = __floats2bfloat162_rn(v.x, v.y);
        dst[i * 2 + 1] = __floats2bfloat162_rn(v.z, v.w);
    }
    g_h[m] = -0.5f * s;
}

__global__ __launch_bounds__(THREADS, 4) void nn_kernel(
    const float* __restrict__ x, float* __restrict__ out)
{
    // static smem: 16K (x) + 2*16K (B double buffer) = 49152 B
    __shared__ __align__(16) char sx[TILE_R * 128];
    __shared__ __align__(16) char sb[2][TILE_N * 128];

    const int tid  = threadIdx.x;
    const int lane = tid & 31;
    const int wid  = tid >> 5;
    const int wr0  = wid * 16;
    const int row0 = blockIdx.x * TILE_R;

    const uint32_t sxu  = smem_u32(sx);
    const uint32_t sbu0 = smem_u32(sb[0]);
    const uint32_t sbu1 = smem_u32(sb[1]);

    // ---- cp.async dst offsets for B fill (4 x 16B per thread, swizzle-fixed) ----
    uint32_t cpo[4];
#pragma unroll
    for (int i = 0; i < 4; i++) {
        int idx = tid + i * THREADS;            // 1024 chunks of 16B
        cpo[i] = swz((idx >> 3) * 128 + (idx & 7) * 16);
    }

    // ---- kick off B tile 0 ----
    {
        const char* src = (const char*)g_codes_bf16;
#pragma unroll
        for (int i = 0; i < 4; i++)
            CP_ASYNC16(sbu0 + cpo[i], src + (size_t)(tid + i * THREADS) * 16);
        CP_COMMIT();
    }

    // ---- x tile fp32->bf16, swizzled (overlaps cp.async) ----
#pragma unroll
    for (int j = 0; j < 16; j++) {
        int idx = tid + j * THREADS;            // 4096 pairs
        int r = idx >> 5, p = idx & 31;
        float2 v = *reinterpret_cast<const float2*>(x + (size_t)(row0 + r) * D_ + p * 2);
        uint32_t pk;
        asm("cvt.rn.bf16x2.f32 %0, %1, %2;" : "=r"(pk) : "f"(v.y), "f"(v.x));
        *reinterpret_cast<uint32_t*>(sx + swz(r * 128 + p * 4)) = pk;
    }
    CP_WAIT0();
    __syncthreads();

    // ---- A fragments for all 4 k-steps (register-resident whole kernel) ----
    uint32_t a[16];
    {
        int arow = wr0 + (lane & 7) + ((lane >> 3) & 1) * 8;
        int akb  = ((lane >> 4) & 1) * 16;
#pragma unroll
        for (int kk = 0; kk < 4; kk++) {
            uint32_t addr = sxu + swz(arow * 128 + kk * 32 + akb);
            LDSM4(a[kk * 4 + 0], a[kk * 4 + 1], a[kk * 4 + 2], a[kk * 4 + 3], addr);
        }
    }

    // ---- precomputed B ldmatrix base addresses (j adds 1024) ----
    const int brl = lane & 7;
    const int bkb = (lane >> 3) * 16;
    const uint32_t bo0 = swz(brl * 128 + bkb);        // k 0..31
    const uint32_t bo1 = swz(brl * 128 + 64 + bkb);   // k 32..63

    const int cq = (lane & 3) * 2;                    // this thread's column pair

    // packed (value | inv-code) keys; max-tracking
    float klo = __uint_as_float(0xFF800000u);         // -inf
    float khi = __uint_as_float(0xFF800000u);

    const float2* hp_base = reinterpret_cast<const float2*>(g_h + cq);

    for (int t = 0; t < NT; t++) {
        const uint32_t sbu = (t & 1) ? sbu1 : sbu0;

        // prefetch next B tile (other buffer) via cp.async
        if (t + 1 < NT) {
            const uint32_t dbu = (t & 1) ? sbu0 : sbu1;
            const char* src = (const char*)g_codes_bf16 + ((size_t)(t + 1) << 14);
#pragma unroll
            for (int i = 0; i < 4; i++)
                CP_ASYNC16(dbu + cpo[i], src + (size_t)(tid + i * THREADS) * 16);
            CP_COMMIT();
        }

        const int invc_t = 4095 - t * TILE_N - cq;

#pragma unroll
        for (int j = 0; j < 16; j++) {         // 16 n-fragments of 8 codes
            uint32_t b0, b1, b2, b3, b4, b5, b6, b7;
            LDSM4(b0, b1, b2, b3, sbu + bo0 + j * 1024);
            LDSM4(b4, b5, b6, b7, sbu + bo1 + j * 1024);

            float2 hp = __ldg(hp_base + (t * TILE_N + j * 8) / 2 * 1);  // h at codes c, c+1

            float d0, d1, d2, d3;              // r = dot - c2/2 (C preloaded with h)
            MMA_INIT(d0, d1, d2, d3, a[0], a[1], a[2], a[3], b0, b1, hp.x, hp.y);
            MMA16816(d0, d1, d2, d3, a[4],  a[5],  a[6],  a[7],  b2, b3);
            MMA16816(d0, d1, d2, d3, a[8],  a[9],  a[10], a[11], b4, b5);
            MMA16816(d0, d1, d2, d3, a[12], a[13], a[14], a[15], b6, b7);

            // key = (r & ~0xFFF) | (4095 - code): min d2 == max key (1 LOP3 + 1 FMAX each)
            const uint32_t ic = (uint32_t)(invc_t - j * 8);
            klo = fmaxf(klo, __uint_as_float((__float_as_uint(d0) & 0xFFFFF000u) | ic));
            klo = fmaxf(klo, __uint_as_float((__float_as_uint(d1) & 0xFFFFF000u) | (ic - 1)));
            khi = fmaxf(khi, __uint_as_float((__float_as_uint(d2) & 0xFFFFF000u) | ic));
            khi = fmaxf(khi, __uint_as_float((__float_as_uint(d3) & 0xFFFFF000u) | (ic - 1)));
        }

        CP_WAIT0();
        __syncthreads();
    }

    // ---- quad reduction (lanes 4k..4k+3 share rows) ----
#pragma unroll
    for (int off = 1; off <= 2; off <<= 1) {
        klo = fmaxf(klo, __shfl_xor_sync(0xffffffffu, klo, off));
        khi = fmaxf(khi, __shfl_xor_sync(0xffffffffu, khi, off));
    }

    if ((lane & 3) == 0) {
        const int rlo = wr0 + (lane >> 2);
        const int rhi = rlo + 8;
        float x2lo = 0.f, x2hi = 0.f;
        const float* xlo = x + (size_t)(row0 + rlo) * D_;
        const float* xhi = x + (size_t)(row0 + rhi) * D_;
#pragma unroll
        for (int i = 0; i < D_ / 4; i++) {
            float4 u = *reinterpret_cast<const float4*>(xlo + i * 4);
            float4 w = *reinterpret_cast<const float4*>(xhi + i * 4);
            x2lo = fmaf(u.x, u.x, x2lo); x2lo = fmaf(u.y, u.y, x2lo);
            x2lo = fmaf(u.z, u.z, x2lo); x2lo = fmaf(u.w, u.w, x2lo);
            x2hi = fmaf(w.x, w.x, x2hi); x2hi = fmaf(w.y, w.y, x2hi);
            x2hi = fmaf(w.z, w.z, x2hi); x2hi = fmaf(w.w, w.w, x2hi);
        }
        uint32_t blo = __float_as_uint(klo), bhi = __float_as_uint(khi);
        float rvlo = __uint_as_float(blo & 0xFFFFF000u);
        float rvhi = __uint_as_float(bhi & 0xFFFFF000u);
        int   clo  = 4095 - (int)(blo & 0xFFFu);
        int   chi  = 4095 - (int)(bhi & 0xFFFu);
        // d2 = x2 - 2*r  (r = dot - c2/2)
        float d2lo = fmaf(-2.f, rvlo, x2lo);
        float d2hi = fmaf(-2.f, rvhi, x2hi);
        out[row0 + rlo] = (d2lo <= 0.1f) ? (float)clo : -1.0f;
        out[row0 + rhi] = (d2hi <= 0.1f) ? (float)chi : -1.0f;
    }
}

extern "C" void kernel_launch(void* const* d_in, const int* in_sizes, int n_in,
                              void* d_out, int out_size) {
    const float* x     = (const float*)d_in[0];  // [16,4096,64] f32
    const float* codes = (const float*)d_in[1];  // [4096,64]    f32
    float* out = (float*)d_out;                  // [16,4096]    f32

    (void)in_sizes; (void)n_in; (void)out_size;

    prep_codes<<<M_ / 256, 256>>>(codes);
    nn_kernel<<<ROWS_ / TILE_R, THREADS>>>(x, out);
}

// round 16
// speedup vs baseline: 11.0209x; 1.1358x over previous
#include <cuda_runtime.h>
#include <cuda_bf16.h>
#include <cstdint>

#define B_ 16
#define N_ 4096
#define M_ 4096
#define D_ 64
#define ROWS_ (B_ * N_)
#define TILE_R 256
#define TILE_N 128
#define NT (M_ / TILE_N)     // 32 code tiles
#define THREADS 256

// ---------------- device globals (no allocation allowed) ----------------
__device__ float         g_h[M_];                 // -0.5 * ||c||^2
__device__ __nv_bfloat16 g_codes_bf16[M_ * D_];

__device__ __forceinline__ uint32_t smem_u32(const void* p) {
    uint32_t a;
    asm("{ .reg .u64 t; cvta.to.shared.u64 t, %1; cvt.u32.u64 %0, t; }" : "=r"(a) : "l"(p));
    return a;
}
// 128B-row swizzle; swz(o + k*1024) == swz(o) + k*1024 (bits 7..9 untouched)
__device__ __forceinline__ uint32_t swz(uint32_t o) { return o ^ ((o >> 3) & 0x70); }
__device__ __forceinline__ uint32_t cvt2(float lo, float hi) {
    uint32_t pk;
    asm("cvt.rn.bf16x2.f32 %0, %1, %2;" : "=r"(pk) : "f"(hi), "f"(lo));
    return pk;
}

#define LDSM4(d0, d1, d2, d3, a)                                                 \
    asm volatile("ldmatrix.sync.aligned.m8n8.x4.shared.b16 {%0,%1,%2,%3}, [%4];" \
        : "=r"(d0), "=r"(d1), "=r"(d2), "=r"(d3) : "r"(a))

#define MMA16816(d0, d1, d2, d3, a0, a1, a2, a3, b0, b1)                         \
    asm volatile("mma.sync.aligned.m16n8k16.row.col.f32.bf16.bf16.f32 "          \
        "{%0,%1,%2,%3}, {%4,%5,%6,%7}, {%8,%9}, {%0,%1,%2,%3};"                  \
        : "+f"(d0), "+f"(d1), "+f"(d2), "+f"(d3)                                 \
        : "r"(a0), "r"(a1), "r"(a2), "r"(a3), "r"(b0), "r"(b1))

// first MMA of the chain: C preloaded with h = -c^2/2 (per-column)
#define MMA_INIT(d0, d1, d2, d3, a0, a1, a2, a3, b0, b1, c0, c1)                 \
    asm volatile("mma.sync.aligned.m16n8k16.row.col.f32.bf16.bf16.f32 "          \
        "{%0,%1,%2,%3}, {%4,%5,%6,%7}, {%8,%9}, {%10,%11,%12,%13};"              \
        : "=f"(d0), "=f"(d1), "=f"(d2), "=f"(d3)                                 \
        : "r"(a0), "r"(a1), "r"(a2), "r"(a3), "r"(b0), "r"(b1),                  \
          "f"(c0), "f"(c1), "f"(c0), "f"(c1))

#define CP_ASYNC16(dst, src) \
    asm volatile("cp.async.cg.shared.global [%0], [%1], 16;" :: "r"(dst), "l"(src) : "memory")
#define CP_COMMIT() asm volatile("cp.async.commit_group;" ::: "memory")
#define CP_WAIT0()  asm volatile("cp.async.wait_group 0;" ::: "memory")

// key = (r & ~0xFFF) | invcode : min d2 == max key (1 LOP3 + 1 FMAX per value)
#define KEYMAX(acc, d, ic) \
    acc = fmaxf(acc, __uint_as_float((__float_as_uint(d) & 0xFFFFF000u) | (ic)))

// ---------------- prepass: h = -c2/2 + bf16 codes ----------------
__global__ void prep_codes(const float* __restrict__ codes) {
    int m = blockIdx.x * blockDim.x + threadIdx.x;
    if (m >= M_) return;
    const float4* p = reinterpret_cast<const float4*>(codes + (size_t)m * D_);
    __nv_bfloat162* dst = reinterpret_cast<__nv_bfloat162*>(g_codes_bf16 + (size_t)m * D_);
    float s = 0.f;
#pragma unroll
    for (int i = 0; i < D_ / 4; i++) {
        float4 v = p[i];
        s = fmaf(v.x, v.x, s); s = fmaf(v.y, v.y, s);
        s = fmaf(v.z, v.z, s); s = fmaf(v.w, v.w, s);
        dst[i * 2]     = __floats2bfloat162_rn(v.x, v.y);
        dst[i * 2 + 1] = __floats2bfloat162_rn(v.z, v.w);
    }
    g_h[m] = -0.5f * s;
}

__global__ __launch_bounds__(THREADS, 2) void nn_kernel(
    const float* __restrict__ x, float* __restrict__ out)
{
    // static smem: 2*16K (B double buffer) + 16K (h table) = 49152 B
    __shared__ __align__(16) char  sb[2][TILE_N * 128];
    __shared__ __align__(16) float sh[M_];

    const int tid  = threadIdx.x;
    const int lane = tid & 31;
    const int wid  = tid >> 5;
    const int wr0  = wid * 32;               // warp owns 32 rows (two m16 blocks)
    const int row0 = blockIdx.x * TILE_R;

    const uint32_t sbu0 = smem_u32(sb[0]);
    const uint32_t sbu1 = smem_u32(sb[1]);

    // ---- cp.async dst offsets for B fill (4 x 16B per thread) ----
    uint32_t cpo[4];
#pragma unroll
    for (int i = 0; i < 4; i++) {
        int idx = tid + i * THREADS;
        cpo[i] = swz((idx >> 3) * 128 + (idx & 7) * 16);
    }

    // ---- kick off B tile 0 ----
    {
        const char* src = (const char*)g_codes_bf16;
#pragma unroll
        for (int i = 0; i < 4; i++)
            CP_ASYNC16(sbu0 + cpo[i], src + (size_t)(tid + i * THREADS) * 16);
        CP_COMMIT();
    }

    // ---- h table to smem (overlaps cp.async) ----
#pragma unroll
    for (int j = 0; j < 4; j++) {
        int idx = tid + j * THREADS;         // 1024 float4
        *reinterpret_cast<float4*>(sh + idx * 4) =
            *reinterpret_cast<const float4*>(g_h + idx * 4);
    }

    // ---- A fragments direct from gmem (PTX m16n8k16 A layout), 2 m-blocks ----
    uint32_t a[2][16];
#pragma unroll
    for (int blk = 0; blk < 2; blk++) {
        const int rl = row0 + wr0 + blk * 16 + (lane >> 2);
        const float2* plo = reinterpret_cast<const float2*>(x + (size_t)rl * D_);
        const float2* phi = plo + 8 * (D_ / 2);   // +8 rows
#pragma unroll
        for (int kk = 0; kk < 4; kk++) {
            const int q = kk * 8 + (lane & 3);    // float2 index (col/2)
            float2 vl0 = plo[q],     vh0 = phi[q];
            float2 vl1 = plo[q + 4], vh1 = phi[q + 4];
            a[blk][kk * 4 + 0] = cvt2(vl0.x, vl0.y);
            a[blk][kk * 4 + 1] = cvt2(vh0.x, vh0.y);
            a[blk][kk * 4 + 2] = cvt2(vl1.x, vl1.y);
            a[blk][kk * 4 + 3] = cvt2(vh1.x, vh1.y);
        }
    }

    CP_WAIT0();
    __syncthreads();

    // ---- precomputed B ldmatrix base addresses (j adds 1024) ----
    const int brl = lane & 7;
    const int bkb = (lane >> 3) * 16;
    const uint32_t bo0 = swz(brl * 128 + bkb);        // k 0..31
    const uint32_t bo1 = swz(brl * 128 + 64 + bkb);   // k 32..63

    const int cq = (lane & 3) * 2;                    // thread's column pair

    // 4 packed-key chains: {blk0,blk1} x {row g, row g+8}
    const float NEGINF = __uint_as_float(0xFF800000u);
    float k00 = NEGINF, k01 = NEGINF, k10 = NEGINF, k11 = NEGINF;

    for (int t = 0; t < NT; t++) {
        const uint32_t sbu = (t & 1) ? sbu1 : sbu0;

        if (t + 1 < NT) {
            const uint32_t dbu = (t & 1) ? sbu0 : sbu1;
            const char* src = (const char*)g_codes_bf16 + ((size_t)(t + 1) << 14);
#pragma unroll
            for (int i = 0; i < 4; i++)
                CP_ASYNC16(dbu + cpo[i], src + (size_t)(tid + i * THREADS) * 16);
            CP_COMMIT();
        }

        const uint32_t invc_t = (uint32_t)(4095 - t * TILE_N - cq);

#pragma unroll
        for (int j = 0; j < 16; j++) {        // 16 n-frags of 8 codes, reused by both blocks
            uint32_t b0, b1, b2, b3, b4, b5, b6, b7;
            LDSM4(b0, b1, b2, b3, sbu + bo0 + j * 1024);
            LDSM4(b4, b5, b6, b7, sbu + bo1 + j * 1024);

            const float2 hp = *reinterpret_cast<const float2*>(sh + t * TILE_N + j * 8 + cq);

            float d0, d1, d2, d3, e0, e1, e2, e3;
            MMA_INIT(d0, d1, d2, d3, a[0][0],  a[0][1],  a[0][2],  a[0][3],  b0, b1, hp.x, hp.y);
            MMA_INIT(e0, e1, e2, e3, a[1][0],  a[1][1],  a[1][2],  a[1][3],  b0, b1, hp.x, hp.y);
            MMA16816(d0, d1, d2, d3, a[0][4],  a[0][5],  a[0][6],  a[0][7],  b2, b3);
            MMA16816(e0, e1, e2, e3, a[1][4],  a[1][5],  a[1][6],  a[1][7],  b2, b3);
            MMA16816(d0, d1, d2, d3, a[0][8],  a[0][9],  a[0][10], a[0][11], b4, b5);
            MMA16816(e0, e1, e2, e3, a[1][8],  a[1][9],  a[1][10], a[1][11], b4, b5);
            MMA16816(d0, d1, d2, d3, a[0][12], a[0][13], a[0][14], a[0][15], b6, b7);
            MMA16816(e0, e1, e2, e3, a[1][12], a[1][13], a[1][14], a[1][15], b6, b7);

            const uint32_t ic = invc_t - (uint32_t)(j * 8);
            KEYMAX(k00, d0, ic); KEYMAX(k00, d1, ic - 1);
            KEYMAX(k01, d2, ic); KEYMAX(k01, d3, ic - 1);
            KEYMAX(k10, e0, ic); KEYMAX(k10, e1, ic - 1);
            KEYMAX(k11, e2, ic); KEYMAX(k11, e3, ic - 1);
        }

        CP_WAIT0();
        __syncthreads();
    }

    // ---- quad reduction (lanes 4k..4k+3 share rows) ----
#pragma unroll
    for (int off = 1; off <= 2; off <<= 1) {
        k00 = fmaxf(k00, __shfl_xor_sync(0xffffffffu, k00, off));
        k01 = fmaxf(k01, __shfl_xor_sync(0xffffffffu, k01, off));
        k10 = fmaxf(k10, __shfl_xor_sync(0xffffffffu, k10, off));
        k11 = fmaxf(k11, __shfl_xor_sync(0xffffffffu, k11, off));
    }

    if ((lane & 3) == 0) {
        const float keys[4] = { k00, k01, k10, k11 };
        const int   rows[4] = { wr0 + (lane >> 2),      wr0 + (lane >> 2) + 8,
                                wr0 + (lane >> 2) + 16, wr0 + (lane >> 2) + 24 };
#pragma unroll
        for (int v = 0; v < 4; v++) {
            const int row = rows[v];
            const float* xr = x + (size_t)(row0 + row) * D_;
            float x2 = 0.f;
#pragma unroll
            for (int i = 0; i < D_ / 4; i++) {
                float4 u = *reinterpret_cast<const float4*>(xr + i * 4);
                x2 = fmaf(u.x, u.x, x2); x2 = fmaf(u.y, u.y, x2);
                x2 = fmaf(u.z, u.z, x2); x2 = fmaf(u.w, u.w, x2);
            }
            const uint32_t kb = __float_as_uint(keys[v]);
            const float rv = __uint_as_float(kb & 0xFFFFF000u);   // r = dot - c2/2
            const int   ci = 4095 - (int)(kb & 0xFFFu);
            const float d2 = fmaf(-2.f, rv, x2);                  // d2 = x2 - 2r
            out[row0 + row] = (d2 <= 0.1f) ? (float)ci : -1.0f;
        }
    }
}

extern "C" void kernel_launch(void* const* d_in, const int* in_sizes, int n_in,
                              void* d_out, int out_size) {
    const float* x     = (const float*)d_in[0];  // [16,4096,64] f32
    const float* codes = (const float*)d_in[1];  // [4096,64]    f32
    float* out = (float*)d_out;                  // [16,4096]    f32

    (void)in_sizes; (void)n_in; (void)out_size;

    prep_codes<<<M_ / 256, 256>>>(codes);
    nn_kernel<<<ROWS_ / TILE_R, THREADS>>>(x, out);
}